// round 3
// baseline (speedup 1.0000x reference)
#include <cuda_runtime.h>
#include <cuda_bf16.h>
#include <float.h>

#define W 128
#define BINS 50
#define NBOUND (BINS - 1)   // 49 inner boundaries
#define THREADS 256
#define NWARP (THREADS / 32)

__global__ __launch_bounds__(THREADS, 6)
void mtf_kernel(const float* __restrict__ X, float* __restrict__ out, int S) {
    __shared__ float bnd[NBOUND];
    __shared__ int   bins[W];
    __shared__ __align__(16) float mtm[BINS * BINS];  // raw transition counts
    __shared__ __align__(16) float G[BINS * W];       // G[b1][t2] = norm mtm[b1][bins[t2]]
    __shared__ float smn[NWARP], smx[NWARP];
    __shared__ float bmn, bmx;
    __shared__ float rowinv[BINS];

    const int s    = blockIdx.x;
    const int tid  = threadIdx.x;
    const int lane = tid & 31;
    const int wid  = tid >> 5;

    if (s >= S) return;

    const float* x = X + (size_t)s * W;

    // Boundaries: linspace(-1, 1, 51)[1:-1].
    if (tid < NBOUND) {
        bnd[tid] = (float)(-1.0 + (2.0 * (double)(tid + 1)) / 50.0);
    }

    // Zero the transition matrix.
    for (int i = tid; i < BINS * BINS; i += THREADS) mtm[i] = 0.0f;

    // Load series value (threads 0..127).
    float v = 0.0f;
    if (tid < W) v = x[tid];

    // --- block min/max over the 128 values ---
    float mn = (tid < W) ? v : FLT_MAX;
    float mx = (tid < W) ? v : -FLT_MAX;
    #pragma unroll
    for (int o = 16; o > 0; o >>= 1) {
        mn = fminf(mn, __shfl_xor_sync(0xFFFFFFFFu, mn, o));
        mx = fmaxf(mx, __shfl_xor_sync(0xFFFFFFFFu, mx, o));
    }
    if (lane == 0) { smn[wid] = mn; smx[wid] = mx; }
    __syncthreads();
    if (wid == 0) {
        float a = (lane < NWARP) ? smn[lane] : FLT_MAX;
        float b = (lane < NWARP) ? smx[lane] : -FLT_MAX;
        #pragma unroll
        for (int o = 4; o > 0; o >>= 1) {
            a = fminf(a, __shfl_xor_sync(0xFFFFFFFFu, a, o));
            b = fmaxf(b, __shfl_xor_sync(0xFFFFFFFFu, b, o));
        }
        if (lane == 0) { bmn = a; bmx = b; }
    }
    __syncthreads();

    // --- scale into [-1, 1] (same op order as reference) and bucketize ---
    if (tid < W) {
        float denom = bmx - bmn + 1e-6f;
        float t = (v - bmn) / denom;
        float xsc = t * 2.0f + (-1.0f);   // t*(hi-lo) + lo
        // searchsorted(side='left') == #{k : bnd[k] < xsc}
        int cnt = 0;
        #pragma unroll
        for (int k = 0; k < NBOUND; k++) cnt += (bnd[k] < xsc) ? 1 : 0;
        bins[tid] = cnt;
    }
    __syncthreads();

    // --- transition histogram ---
    if (tid < W - 1) {
        atomicAdd(&mtm[bins[tid] * BINS + bins[tid + 1]], 1.0f);
    }
    __syncthreads();

    // --- row sums -> reciprocals (empty rows -> divide by 1) ---
    if (tid < BINS) {
        float sum = 0.0f;
        const float* row = &mtm[tid * BINS];
        #pragma unroll
        for (int k = 0; k < BINS; k++) sum += row[k];
        rowinv[tid] = (sum == 0.0f) ? 1.0f : (1.0f / sum);
    }
    __syncthreads();

    // --- build G[b1][t2] = mtm[b1][bins[t2]] * rowinv[b1] ---
    {
        int c0 = bins[lane];
        int c1 = bins[lane + 32];
        int c2 = bins[lane + 64];
        int c3 = bins[lane + 96];
        for (int b1 = wid; b1 < BINS; b1 += NWARP) {
            const float* row = &mtm[b1 * BINS];
            float rinv = rowinv[b1];
            float* g = &G[b1 * W];
            g[lane]      = row[c0] * rinv;
            g[lane + 32] = row[c1] * rinv;
            g[lane + 64] = row[c2] * rinv;
            g[lane + 96] = row[c3] * rinv;
        }
    }
    __syncthreads();

    // --- write output: out[t1][:] = G[bins[t1]][:], one row per warp-iter ---
    float* o = out + (size_t)s * W * W;
    for (int t1 = wid; t1 < W; t1 += NWARP) {
        const float4* g = reinterpret_cast<const float4*>(&G[bins[t1] * W]);
        float4* dst = reinterpret_cast<float4*>(o + t1 * W);
        dst[lane] = g[lane];
    }
}

extern "C" void kernel_launch(void* const* d_in, const int* in_sizes, int n_in,
                              void* d_out, int out_size) {
    const float* X = (const float*)d_in[0];
    float* out = (float*)d_out;
    int S = in_sizes[0] / W;   // 256*6 = 1536 series
    mtf_kernel<<<S, THREADS>>>(X, out, S);
}

// round 4
// speedup vs baseline: 1.5511x; 1.5511x over previous
#include <cuda_runtime.h>
#include <cuda_bf16.h>
#include <float.h>

#define W 128
#define BINS 50
#define NBOUND (BINS - 1)
#define MPAD 64              // padded row stride for mtm
#define THREADS 256
#define NWARP (THREADS / 32)

__global__ __launch_bounds__(THREADS, 8)
void mtf_kernel(const float* __restrict__ X, float* __restrict__ out, int S) {
    __shared__ float bnd[NBOUND];
    __shared__ int   bins[W];
    __shared__ float mtm[BINS * MPAD];     // padded: bank(c) = c mod 32
    __shared__ float smn[NWARP], smx[NWARP];
    __shared__ float bmn, bmx;

    const int s    = blockIdx.x;
    const int tid  = threadIdx.x;
    const int lane = tid & 31;
    const int wid  = tid >> 5;

    if (s >= S) return;

    const float* x = X + (size_t)s * W;

    // Boundaries: linspace(-1, 1, 51)[1:-1].
    if (tid < NBOUND) {
        bnd[tid] = (float)(-1.0 + (2.0 * (double)(tid + 1)) / 50.0);
    }
    // Zero transition counts.
    for (int i = tid; i < BINS * MPAD; i += THREADS) mtm[i] = 0.0f;

    // Load series value (threads 0..127) and block min/max.
    float v = 0.0f;
    if (tid < W) v = x[tid];
    float mn = (tid < W) ? v : FLT_MAX;
    float mx = (tid < W) ? v : -FLT_MAX;
    #pragma unroll
    for (int o = 16; o > 0; o >>= 1) {
        mn = fminf(mn, __shfl_xor_sync(0xFFFFFFFFu, mn, o));
        mx = fmaxf(mx, __shfl_xor_sync(0xFFFFFFFFu, mx, o));
    }
    if (lane == 0) { smn[wid] = mn; smx[wid] = mx; }
    __syncthreads();                                   // S1
    if (wid == 0) {
        float a = (lane < NWARP) ? smn[lane] : FLT_MAX;
        float b = (lane < NWARP) ? smx[lane] : -FLT_MAX;
        #pragma unroll
        for (int o = 4; o > 0; o >>= 1) {
            a = fminf(a, __shfl_xor_sync(0xFFFFFFFFu, a, o));
            b = fmaxf(b, __shfl_xor_sync(0xFFFFFFFFu, b, o));
        }
        if (lane == 0) { bmn = a; bmx = b; }
    }
    __syncthreads();                                   // S2

    // Scale into [-1,1] (same op order as reference) and bucketize.
    if (tid < W) {
        float denom = bmx - bmn + 1e-6f;
        float t = (v - bmn) / denom;
        float xsc = t * 2.0f + (-1.0f);
        int cnt = 0;
        #pragma unroll
        for (int k = 0; k < NBOUND; k++) cnt += (bnd[k] < xsc) ? 1 : 0;
        bins[tid] = cnt;
    }
    __syncthreads();                                   // S3

    // Transition histogram (padded rows).
    if (tid < W - 1) {
        atomicAdd(&mtm[bins[tid] * MPAD + bins[tid + 1]], 1.0f);
    }
    // Every lane caches the 4 column-bin indices it is responsible for.
    int c0 = bins[lane];
    int c1 = bins[lane + 32];
    int c2 = bins[lane + 64];
    int c3 = bins[lane + 96];
    __syncthreads();                                   // S4

    // For each bin-row this warp owns: row-sum (lane-parallel), gather+scale
    // into registers, then ballot-match destination rows and store directly.
    float* o = out + (size_t)s * W * W;
    for (int b1 = wid; b1 < BINS; b1 += NWARP) {
        const float* row = &mtm[b1 * MPAD];

        // row sum over 50 entries: lanes 0..31 + lanes 0..17 again at +32
        float part = row[lane] + ((lane < BINS - 32) ? row[lane + 32] : 0.0f);
        #pragma unroll
        for (int off = 16; off > 0; off >>= 1)
            part += __shfl_xor_sync(0xFFFFFFFFu, part, off);
        float rinv = (part == 0.0f) ? 1.0f : (1.0f / part);

        // gather normalized row values for this lane's 4 output columns
        float v0 = row[c0] * rinv;
        float v1 = row[c1] * rinv;
        float v2 = row[c2] * rinv;
        float v3 = row[c3] * rinv;

        // find all t1 with bins[t1] == b1 and store the row there
        unsigned m0 = __ballot_sync(0xFFFFFFFFu, c0 == b1);
        unsigned m1 = __ballot_sync(0xFFFFFFFFu, c1 == b1);
        unsigned m2 = __ballot_sync(0xFFFFFFFFu, c2 == b1);
        unsigned m3 = __ballot_sync(0xFFFFFFFFu, c3 == b1);
        while (m0) {
            int t1 = __ffs(m0) - 1; m0 &= m0 - 1;
            float* d = o + t1 * W + lane;
            d[0] = v0; d[32] = v1; d[64] = v2; d[96] = v3;
        }
        while (m1) {
            int t1 = 32 + __ffs(m1) - 1; m1 &= m1 - 1;
            float* d = o + t1 * W + lane;
            d[0] = v0; d[32] = v1; d[64] = v2; d[96] = v3;
        }
        while (m2) {
            int t1 = 64 + __ffs(m2) - 1; m2 &= m2 - 1;
            float* d = o + t1 * W + lane;
            d[0] = v0; d[32] = v1; d[64] = v2; d[96] = v3;
        }
        while (m3) {
            int t1 = 96 + __ffs(m3) - 1; m3 &= m3 - 1;
            float* d = o + t1 * W + lane;
            d[0] = v0; d[32] = v1; d[64] = v2; d[96] = v3;
        }
    }
}

extern "C" void kernel_launch(void* const* d_in, const int* in_sizes, int n_in,
                              void* d_out, int out_size) {
    const float* X = (const float*)d_in[0];
    float* out = (float*)d_out;
    int S = in_sizes[0] / W;   // 256*6 = 1536 series
    mtf_kernel<<<S, THREADS>>>(X, out, S);
}